// round 4
// baseline (speedup 1.0000x reference)
#include <cuda_runtime.h>
#include <cuda_bf16.h>
#include <math.h>

// Problem constants
#define BB 256
#define SS 512
#define KK 20
#define DD 256
#define KPAD 24   // padded row length for [d][k] transposed state arrays (96B rows, 16B aligned)

// Precomputed scratch (static device globals: allocation-free)
__device__ float g_xw[(size_t)BB * SS * DD];   // xW[b][s][e]   (134 MB)
__device__ float g_xk[(size_t)BB * SS * KK];   // x.keys[b][s][k] (10.5 MB)

// ---------------- packed f32x2 helpers ----------------
__device__ __forceinline__ unsigned long long f2fma(unsigned long long a,
                                                    unsigned long long b,
                                                    unsigned long long c) {
    unsigned long long d;
    asm("fma.rn.f32x2 %0, %1, %2, %3;" : "=l"(d) : "l"(a), "l"(b), "l"(c));
    return d;
}
__device__ __forceinline__ unsigned long long pk2(float a) {
    unsigned int ai = __float_as_uint(a);
    return (((unsigned long long)ai) << 32) | (unsigned long long)ai;
}
__device__ __forceinline__ void upk2(unsigned long long p, float& lo, float& hi) {
    unsigned int l = (unsigned int)(p & 0xffffffffull);
    unsigned int h = (unsigned int)(p >> 32);
    lo = __uint_as_float(l);
    hi = __uint_as_float(h);
}

// ---------------- shared memory layout (main kernel) ----------------
struct SmemMain {
    float h_T[DD][KPAD];      // h transposed: h_T[d][k]
    float kV_T[DD][KPAD];     // kV transposed
    float accT0[KK * DD];     // GEMM partials, d-half 0   (also reused as keys_T staging at init)
    float accT1[KK * DD];     // GEMM partials, d-half 1   (contiguous with accT0)
    float red[8][2 * KK];     // merged reduction partials: [0..19]=sq, [20..39]=du
    float rbuf[KK];           // rinv broadcast
    float gbuf[KK];           // gate broadcast
    unsigned short slist[SS]; // active step indices
    int wcnt[8];              // compaction scratch
};

// out[k] = sum_d A[d][k] * Mg[d*256 + e]   (init/kV path; full d range, 1 column per thread)
__device__ __forceinline__ void mm20(const float (*A)[KPAD], const float* __restrict__ Mg,
                                     int e, float out[KK]) {
    unsigned long long acc[10];
#pragma unroll
    for (int i = 0; i < 10; i++) acc[i] = 0ull;
    float ua[4], ub[4], un[4];
#pragma unroll
    for (int j = 0; j < 4; j++) ua[j] = Mg[j * DD + e];
#pragma unroll
    for (int j = 0; j < 4; j++) ub[j] = Mg[(4 + j) * DD + e];
    for (int db = 0; db < 64; db++) {
        const int dn = db * 4 + 8;
        if (dn < DD) {
#pragma unroll
            for (int j = 0; j < 4; j++) un[j] = Mg[(dn + j) * DD + e];
        } else {
#pragma unroll
            for (int j = 0; j < 4; j++) un[j] = 0.f;
        }
#pragma unroll
        for (int dd = 0; dd < 4; dd++) {
            const int d = db * 4 + dd;
            const ulonglong2* hr = (const ulonglong2*)A[d];
            ulonglong2 p0 = hr[0], p1 = hr[1], p2 = hr[2], p3 = hr[3], p4 = hr[4];
            unsigned long long uu = pk2(ua[dd]);
            acc[0] = f2fma(p0.x, uu, acc[0]);
            acc[1] = f2fma(p0.y, uu, acc[1]);
            acc[2] = f2fma(p1.x, uu, acc[2]);
            acc[3] = f2fma(p1.y, uu, acc[3]);
            acc[4] = f2fma(p2.x, uu, acc[4]);
            acc[5] = f2fma(p2.y, uu, acc[5]);
            acc[6] = f2fma(p3.x, uu, acc[6]);
            acc[7] = f2fma(p3.y, uu, acc[7]);
            acc[8] = f2fma(p4.x, uu, acc[8]);
            acc[9] = f2fma(p4.y, uu, acc[9]);
        }
#pragma unroll
        for (int j = 0; j < 4; j++) { ua[j] = ub[j]; ub[j] = un[j]; }
    }
#pragma unroll
    for (int i = 0; i < 10; i++) upk2(acc[i], out[2 * i], out[2 * i + 1]);
}

// ---------------- kernel 1: xW[b][s][:] = x @ W ----------------
__global__ void __launch_bounds__(256) xw_kernel(const float* __restrict__ X,
                                                 const float* __restrict__ W) {
    __shared__ float xt[DD][34];
    const int cta = blockIdx.x;
    const int b = cta >> 4;
    const int s0 = (cta & 15) * 32;
    const int tid = threadIdx.x;

    for (int idx = tid; idx < 32 * DD; idx += 256) {
        const int ss = idx >> 8, d = idx & 255;
        xt[d][ss] = X[((size_t)(b * SS + s0 + ss)) * DD + d];
    }
    __syncthreads();

    unsigned long long acc[16];
#pragma unroll
    for (int i = 0; i < 16; i++) acc[i] = 0ull;

    float ua[4], ub[4], un[4];
#pragma unroll
    for (int j = 0; j < 4; j++) ua[j] = W[j * DD + tid];
#pragma unroll
    for (int j = 0; j < 4; j++) ub[j] = W[(4 + j) * DD + tid];
    for (int db = 0; db < 64; db++) {
        const int dn = db * 4 + 8;
        if (dn < DD) {
#pragma unroll
            for (int j = 0; j < 4; j++) un[j] = W[(dn + j) * DD + tid];
        } else {
#pragma unroll
            for (int j = 0; j < 4; j++) un[j] = 0.f;
        }
#pragma unroll
        for (int dd = 0; dd < 4; dd++) {
            const int d = db * 4 + dd;
            const unsigned long long* xr = (const unsigned long long*)xt[d];
            unsigned long long ww = pk2(ua[dd]);
#pragma unroll
            for (int j = 0; j < 16; j++) acc[j] = f2fma(xr[j], ww, acc[j]);
        }
#pragma unroll
        for (int j = 0; j < 4; j++) { ua[j] = ub[j]; ub[j] = un[j]; }
    }
#pragma unroll
    for (int j = 0; j < 16; j++) {
        float lo, hi;
        upk2(acc[j], lo, hi);
        g_xw[((size_t)b * SS + s0 + 2 * j) * DD + tid] = lo;
        g_xw[((size_t)b * SS + s0 + 2 * j + 1) * DD + tid] = hi;
    }
}

// ---------------- kernel 1b: xk[b][s][k] = x . keys[b][k]  (one warp per (b,s)) ----------------
__global__ void __launch_bounds__(256) xk_kernel(const float* __restrict__ X,
                                                 const float* __restrict__ keys) {
    const int b = blockIdx.x >> 6;
    const int s = ((blockIdx.x & 63) << 3) + (threadIdx.x >> 5);
    const int lane = threadIdx.x & 31;
    const float* x = X + ((size_t)b * SS + s) * DD;
    const float* kb = keys + (size_t)b * KK * DD;

    float xr[8];
#pragma unroll
    for (int c = 0; c < 8; c++) xr[c] = x[lane + 32 * c];

    float pk[KK];
#pragma unroll
    for (int k = 0; k < KK; k++) {
        float p = 0.f;
#pragma unroll
        for (int c = 0; c < 8; c++) p = fmaf(xr[c], kb[k * DD + lane + 32 * c], p);
        pk[k] = p;
    }
#pragma unroll
    for (int o = 16; o; o >>= 1)
#pragma unroll
        for (int k = 0; k < KK; k++) pk[k] += __shfl_xor_sync(0xffffffffu, pk[k], o);

    if (lane < KK)
        g_xk[((size_t)b * SS + s) * KK + lane] = pk[lane];
}

// ---------------- kernel 2: persistent recurrent kernel, 1 CTA per batch b ----------------
__global__ void __launch_bounds__(256, 2) rnn_kernel(const float* __restrict__ X,
                                                     const int* __restrict__ mask,
                                                     const float* __restrict__ keys,
                                                     const float* __restrict__ U,
                                                     const float* __restrict__ V,
                                                     float* __restrict__ out) {
    extern __shared__ unsigned char smraw[];
    SmemMain* sm = (SmemMain*)smraw;
    const int b = blockIdx.x;
    const int tid = threadIdx.x;
    const int lane = tid & 31, warp = tid >> 5;

    // ---- phase 0a: mask compaction into active-step list ----
    int n_act = 0;
    {
        int total = 0;
#pragma unroll
        for (int r = 0; r < 2; r++) {
            const int idx = r * 256 + tid;
            const int m = (mask[b * SS + idx] != 0);
            const unsigned bal = __ballot_sync(0xffffffffu, m);
            const int pre = __popc(bal & ((1u << lane) - 1));
            if (lane == 0) sm->wcnt[warp] = __popc(bal);
            __syncthreads();
            int woff = 0;
            for (int w = 0; w < warp; w++) woff += sm->wcnt[w];
            if (m) sm->slist[total + woff + pre] = (unsigned short)idx;
            int rt = 0;
#pragma unroll
            for (int w = 0; w < 8; w++) rt += sm->wcnt[w];
            total += rt;
            __syncthreads();
        }
        n_act = total;
    }

    // ---- phase 0b: stage keys transposed (into accT region), compute kV, zero h ----
    float (*keys_T)[KPAD] = (float (*)[KPAD])sm->accT0;   // 24KB fits in accT0+accT1 (40KB)
    const float* kb = keys + (size_t)b * KK * DD;
    for (int idx = tid; idx < KK * DD; idx += 256) {
        const int k = idx >> 8, d = idx & 255;
        keys_T[d][k] = kb[idx];
    }
    __syncthreads();
    {
        float kv[KK];
        mm20(keys_T, V, tid, kv);
        __syncthreads();   // all reads of keys_T done before accT reuse
#pragma unroll
        for (int k = 0; k < KK; k++) {
            sm->kV_T[tid][k] = kv[k];
            sm->h_T[tid][k] = 0.f;
        }
    }
    // first gate: h0 = 0 -> g = sigmoid(x_{s1} . keys) = sigmoid(xk[s1])
    if (tid < KK && n_act > 0)
        sm->gbuf[tid] = 1.f / (1.f + __expf(-g_xk[((size_t)b * SS + sm->slist[0]) * KK + tid]));
    __syncthreads();

    const float* xb = X + (size_t)b * SS * DD;
    const float* xwb = g_xw + (size_t)b * SS * DD;

    const int half = tid >> 7;            // d-range
    const int col = tid & 127;            // e-pair (2col, 2col+1)
    const int d0 = half * 128;
    const float2* Up = (const float2*)U + col;
    float2* accW = (float2*)(half ? sm->accT1 : sm->accT0) + col;

    for (int i = 0; i < n_act; i++) {
        const int s = sm->slist[i];
        const bool has_next = (i + 1 < n_act);
        const int sn = has_next ? sm->slist[i + 1] : 0;
        const float xw = xwb[s * DD + tid];
        const float xn = has_next ? xb[sn * DD + tid] : 0.f;

        // ---- hU GEMM, e-pair x d-half blocked; partials to accT0/accT1 ----
        {
            unsigned long long a0[10], a1[10];
#pragma unroll
            for (int q = 0; q < 10; q++) { a0[q] = 0ull; a1[q] = 0ull; }

            float2 ua[4], ub[4], un[4];
#pragma unroll
            for (int j = 0; j < 4; j++) ua[j] = Up[(d0 + j) * 128];
#pragma unroll
            for (int j = 0; j < 4; j++) ub[j] = Up[(d0 + 4 + j) * 128];
            for (int db = 0; db < 32; db++) {
                const int dnb = db * 4 + 8;
                if (dnb < 128) {
#pragma unroll
                    for (int j = 0; j < 4; j++) un[j] = Up[(d0 + dnb + j) * 128];
                } else {
#pragma unroll
                    for (int j = 0; j < 4; j++) un[j] = make_float2(0.f, 0.f);
                }
#pragma unroll
                for (int dd = 0; dd < 4; dd++) {
                    const int d = d0 + db * 4 + dd;
                    const ulonglong2* hr = (const ulonglong2*)sm->h_T[d];
                    ulonglong2 p0 = hr[0], p1 = hr[1], p2 = hr[2], p3 = hr[3], p4 = hr[4];
                    unsigned long long u0 = pk2(ua[dd].x);
                    unsigned long long u1 = pk2(ua[dd].y);
                    a0[0] = f2fma(p0.x, u0, a0[0]);  a1[0] = f2fma(p0.x, u1, a1[0]);
                    a0[1] = f2fma(p0.y, u0, a0[1]);  a1[1] = f2fma(p0.y, u1, a1[1]);
                    a0[2] = f2fma(p1.x, u0, a0[2]);  a1[2] = f2fma(p1.x, u1, a1[2]);
                    a0[3] = f2fma(p1.y, u0, a0[3]);  a1[3] = f2fma(p1.y, u1, a1[3]);
                    a0[4] = f2fma(p2.x, u0, a0[4]);  a1[4] = f2fma(p2.x, u1, a1[4]);
                    a0[5] = f2fma(p2.y, u0, a0[5]);  a1[5] = f2fma(p2.y, u1, a1[5]);
                    a0[6] = f2fma(p3.x, u0, a0[6]);  a1[6] = f2fma(p3.x, u1, a1[6]);
                    a0[7] = f2fma(p3.y, u0, a0[7]);  a1[7] = f2fma(p3.y, u1, a1[7]);
                    a0[8] = f2fma(p4.x, u0, a0[8]);  a1[8] = f2fma(p4.x, u1, a1[8]);
                    a0[9] = f2fma(p4.y, u0, a0[9]);  a1[9] = f2fma(p4.y, u1, a1[9]);
                }
#pragma unroll
                for (int j = 0; j < 4; j++) { ua[j] = ub[j]; ub[j] = un[j]; }
            }
#pragma unroll
            for (int q = 0; q < 10; q++) {
                float l0, h0f, l1, h1f;
                upk2(a0[q], l0, h0f);
                upk2(a1[q], l1, h1f);
                accW[(2 * q) * 128] = make_float2(l0, l1);
                accW[(2 * q + 1) * 128] = make_float2(h0f, h1f);
            }
        }
        __syncthreads();   // bar1: accT ready

        // ---- update: upd = h + g*relu(acc + kV + xw); partials sq & du(next-gate) ----
        float upd[KK], v[2 * KK];
        {
            const float4* h4 = (const float4*)sm->h_T[tid];
            const float4* c4 = (const float4*)sm->kV_T[tid];
#pragma unroll
            for (int q = 0; q < 5; q++) {
                float4 hv = h4[q], cv = c4[q];
                float hvv[4] = {hv.x, hv.y, hv.z, hv.w};
                float cvv[4] = {cv.x, cv.y, cv.z, cv.w};
#pragma unroll
                for (int j = 0; j < 4; j++) {
                    const int k = 4 * q + j;
                    float a = sm->accT0[k * DD + tid] + sm->accT1[k * DD + tid];
                    float t = a + cvv[j] + xw;
                    t = fmaxf(t, 0.f);
                    float u = hvv[j] + sm->gbuf[k] * t;
                    upd[k] = u;
                    v[k] = u * u;          // squared-norm partial
                    v[KK + k] = xn * u;    // next-gate dot partial
                }
            }
        }

        // ---- merged reduce40 ----
#pragma unroll
        for (int o = 16; o; o >>= 1)
#pragma unroll
            for (int k = 0; k < 2 * KK; k++) v[k] += __shfl_xor_sync(0xffffffffu, v[k], o);
        if (lane == 0) {
#pragma unroll
            for (int k = 0; k < 2 * KK; k++) sm->red[warp][k] = v[k];
        }
        __syncthreads();   // bar2
        if (tid < KK) {
            float sq = 0.f, du = 0.f;
#pragma unroll
            for (int w = 0; w < 8; w++) { sq += sm->red[w][tid]; du += sm->red[w][KK + tid]; }
            const float rinv = rsqrtf(fmaxf(sq, 1e-12f));
            sm->rbuf[tid] = rinv;
            if (has_next) {
                const float pre = rinv * du + g_xk[((size_t)b * SS + sn) * KK + tid];
                sm->gbuf[tid] = 1.f / (1.f + __expf(-pre));
            }
        }
        __syncthreads();   // bar3

        // ---- normalize + write back h ----
        {
            float4* h4 = (float4*)sm->h_T[tid];
#pragma unroll
            for (int q = 0; q < 5; q++) {
                float4 t;
                t.x = upd[4 * q + 0] * sm->rbuf[4 * q + 0];
                t.y = upd[4 * q + 1] * sm->rbuf[4 * q + 1];
                t.z = upd[4 * q + 2] * sm->rbuf[4 * q + 2];
                t.w = upd[4 * q + 3] * sm->rbuf[4 * q + 3];
                h4[q] = t;
            }
        }
        __syncthreads();   // bar4: h stable for next GEMM
    }

    // emit h_T -> out[b][k][d]
#pragma unroll
    for (int k = 0; k < KK; k++)
        out[((size_t)b * KK + k) * DD + tid] = sm->h_T[tid][k];
}

extern "C" void kernel_launch(void* const* d_in, const int* in_sizes, int n_in,
                              void* d_out, int out_size) {
    const float* X = (const float*)d_in[0];                    // [B,S,D] f32
    const int* mask = (const int*)d_in[1];                     // [B,S] bool delivered as int32
    const float* keys = (const float*)d_in[2];                 // [B,K,D] f32
    const float* U = (const float*)d_in[3];                    // [D,D] f32
    const float* V = (const float*)d_in[4];                    // [D,D] f32
    const float* W = (const float*)d_in[5];                    // [D,D] f32
    float* out = (float*)d_out;                                // [B,K,D] f32

    const int smem = (int)sizeof(SmemMain);
    cudaFuncSetAttribute(rnn_kernel, cudaFuncAttributeMaxDynamicSharedMemorySize, smem);

    xw_kernel<<<BB * (SS / 32), 256>>>(X, W);
    xk_kernel<<<BB * (SS / 8), 256>>>(X, keys);
    rnn_kernel<<<BB, 256, smem>>>(X, mask, keys, U, V, out);
}

// round 7
// speedup vs baseline: 1.1451x; 1.1451x over previous
#include <cuda_runtime.h>
#include <cuda_bf16.h>
#include <math.h>
#include <stdint.h>

// Problem constants
#define BB 256
#define SS 512
#define KK 20
#define DD 256
#define PITCHB 528   // bytes per bf16 row (264 elems): 16B-aligned, ldmatrix conflict-free
#define PITCHA 132   // f32 elems per accT row

// Precomputed scratch (static device globals: allocation-free)
__device__ float g_xw[(size_t)BB * SS * DD];   // xW[b][s][e]
__device__ float g_xk[(size_t)BB * SS * KK];   // x.keys[b][s][k]

// ================= packed f32x2 helpers (xw kernel) =================
__device__ __forceinline__ unsigned long long f2fma(unsigned long long a,
                                                    unsigned long long b,
                                                    unsigned long long c) {
    unsigned long long d;
    asm("fma.rn.f32x2 %0, %1, %2, %3;" : "=l"(d) : "l"(a), "l"(b), "l"(c));
    return d;
}
__device__ __forceinline__ unsigned long long pk2(float a) {
    unsigned int ai = __float_as_uint(a);
    return (((unsigned long long)ai) << 32) | (unsigned long long)ai;
}
__device__ __forceinline__ void upk2(unsigned long long p, float& lo, float& hi) {
    lo = __uint_as_float((unsigned int)(p & 0xffffffffull));
    hi = __uint_as_float((unsigned int)(p >> 32));
}

// ================= PTX helpers =================
__device__ __forceinline__ uint32_t smem_u32(const void* p) {
    uint32_t a;
    asm("{ .reg .u64 t; cvta.to.shared.u64 t, %1; cvt.u32.u64 %0, t; }" : "=r"(a) : "l"(p));
    return a;
}
__device__ __forceinline__ uint32_t cluster_rank() {
    uint32_t r;
    asm("mov.u32 %0, %%cluster_ctarank;" : "=r"(r));
    return r;
}
#define CLUSTER_SYNC() do { \
    asm volatile("barrier.cluster.arrive.aligned;" ::: "memory"); \
    asm volatile("barrier.cluster.wait.aligned;" ::: "memory"); \
} while (0)

#define LDSM4(r, addr) \
    asm volatile("ldmatrix.sync.aligned.m8n8.x4.shared.b16 {%0,%1,%2,%3}, [%4];" \
        : "=r"((r)[0]), "=r"((r)[1]), "=r"((r)[2]), "=r"((r)[3]) : "r"(addr))

#define MMA16816(c, a, b0, b1) \
    asm volatile("mma.sync.aligned.m16n8k16.row.col.f32.bf16.bf16.f32 " \
        "{%0,%1,%2,%3}, {%4,%5,%6,%7}, {%8,%9}, {%0,%1,%2,%3};" \
        : "+f"((c)[0]), "+f"((c)[1]), "+f"((c)[2]), "+f"((c)[3]) \
        : "r"((a)[0]), "r"((a)[1]), "r"((a)[2]), "r"((a)[3]), "r"(b0), "r"(b1))

// ================= shared memory layout (dynamic) =================
struct MiscS {
    float red[8][2 * KK];      // per-warp merged partials (sq | du)
    float tot[2 * KK];         // CTA-local totals
    float rpart[2 * KK];       // peer partials (written via DSMEM)
    float gbuf[KK];            // gate broadcast
    float rbuf[KK];            // rinv broadcast
    unsigned short slist[SS];  // active step indices
    int wcnt[8];
};
#define OFF_UTHI 0
#define OFF_UTLO (128 * PITCHB)
#define OFF_HAHI (2 * 128 * PITCHB)
#define OFF_HALO (OFF_HAHI + 32 * PITCHB)
#define OFF_ACCT (OFF_HALO + 32 * PITCHB)
#define OFF_MISC (OFF_ACCT + KK * PITCHA * 4)
#define SMEM_TOT ((int)(OFF_MISC + sizeof(MiscS)))

// ================= kernel 1: xW[b][s][:] = x @ W =================
__global__ void __launch_bounds__(256) xw_kernel(const float* __restrict__ X,
                                                 const float* __restrict__ W) {
    __shared__ float xt[DD][34];
    const int cta = blockIdx.x;
    const int b = cta >> 4;
    const int s0 = (cta & 15) * 32;
    const int tid = threadIdx.x;

    for (int idx = tid; idx < 32 * DD; idx += 256) {
        const int ss = idx >> 8, d = idx & 255;
        xt[d][ss] = X[((size_t)(b * SS + s0 + ss)) * DD + d];
    }
    __syncthreads();

    unsigned long long acc[16];
#pragma unroll
    for (int i = 0; i < 16; i++) acc[i] = 0ull;

    float ua[4], ub[4], un[4];
#pragma unroll
    for (int j = 0; j < 4; j++) ua[j] = W[j * DD + tid];
#pragma unroll
    for (int j = 0; j < 4; j++) ub[j] = W[(4 + j) * DD + tid];
    for (int db = 0; db < 64; db++) {
        const int dn = db * 4 + 8;
        if (dn < DD) {
#pragma unroll
            for (int j = 0; j < 4; j++) un[j] = W[(dn + j) * DD + tid];
        } else {
#pragma unroll
            for (int j = 0; j < 4; j++) un[j] = 0.f;
        }
#pragma unroll
        for (int dd = 0; dd < 4; dd++) {
            const int d = db * 4 + dd;
            const unsigned long long* xr = (const unsigned long long*)xt[d];
            unsigned long long ww = pk2(ua[dd]);
#pragma unroll
            for (int j = 0; j < 16; j++) acc[j] = f2fma(xr[j], ww, acc[j]);
        }
#pragma unroll
        for (int j = 0; j < 4; j++) { ua[j] = ub[j]; ub[j] = un[j]; }
    }
#pragma unroll
    for (int j = 0; j < 16; j++) {
        float lo, hi;
        upk2(acc[j], lo, hi);
        g_xw[((size_t)b * SS + s0 + 2 * j) * DD + tid] = lo;
        g_xw[((size_t)b * SS + s0 + 2 * j + 1) * DD + tid] = hi;
    }
}

// ================= kernel 1b: xk[b][s][k] = x . keys[b][k] =================
__global__ void __launch_bounds__(256) xk_kernel(const float* __restrict__ X,
                                                 const float* __restrict__ keys) {
    const int b = blockIdx.x >> 6;
    const int s = ((blockIdx.x & 63) << 3) + (threadIdx.x >> 5);
    const int lane = threadIdx.x & 31;
    const float* x = X + ((size_t)b * SS + s) * DD;
    const float* kb = keys + (size_t)b * KK * DD;

    float xr[8];
#pragma unroll
    for (int c = 0; c < 8; c++) xr[c] = x[lane + 32 * c];

    float pk[KK];
#pragma unroll
    for (int k = 0; k < KK; k++) {
        float p = 0.f;
#pragma unroll
        for (int c = 0; c < 8; c++) p = fmaf(xr[c], kb[k * DD + lane + 32 * c], p);
        pk[k] = p;
    }
#pragma unroll
    for (int o = 16; o; o >>= 1)
#pragma unroll
        for (int k = 0; k < KK; k++) pk[k] += __shfl_xor_sync(0xffffffffu, pk[k], o);

    if (lane < KK)
        g_xk[((size_t)b * SS + s) * KK + lane] = pk[lane];
}

// ================= kernel 2: HMMA recurrent kernel (cluster of 2 per batch) =================
// CTA rank r owns e in [128r, 128r+128). GEMM: C[k][e] = sum_d h[k][d] * U[d][e]
// A = h [32 x 256] bf16 hi/lo tiles in smem (rows 20..31 zero, peer d-half via DSMEM).
// B = U^T e-half [128 x 256] bf16 hi/lo in smem (loaded once).
// 3 passes: AhBh + AhBl + AlBh. fp32 h state in regs (10 k per thread).
__global__ void __launch_bounds__(256, 1) __cluster_dims__(2, 1, 1)
rnn_mma_kernel(const float* __restrict__ X, const int* __restrict__ mask,
               const float* __restrict__ keys, const float* __restrict__ U,
               const float* __restrict__ V, float* __restrict__ out) {
    extern __shared__ __align__(16) unsigned char smraw[];
    MiscS* ms = (MiscS*)(smraw + OFF_MISC);
    float* accT = (float*)(smraw + OFF_ACCT);

    const int tid = threadIdx.x;
    const int lane = tid & 31, w = tid >> 5;
    const int b = blockIdx.x >> 1;
    const uint32_t rank = cluster_rank();
    const int eloc = tid & 127;          // update-phase e column (local)
    const int kh = tid >> 7;             // update-phase k-half (k = 10*kh + j)
    const int eg = (int)rank * 128 + eloc;

    const uint32_t smbase = smem_u32(smraw);

    // ---- mask compaction ----
    int n_act = 0;
    {
        int total = 0;
        for (int r = 0; r < 2; r++) {
            const int idx = r * 256 + tid;
            const int m = (mask[b * SS + idx] != 0);
            const unsigned bal = __ballot_sync(0xffffffffu, m);
            const int pre = __popc(bal & ((1u << lane) - 1));
            if (lane == 0) ms->wcnt[w] = __popc(bal);
            __syncthreads();
            int woff = 0;
            for (int ww = 0; ww < w; ww++) woff += ms->wcnt[ww];
            if (m) ms->slist[total + woff + pre] = (unsigned short)idx;
            int rt = 0;
#pragma unroll
            for (int ww = 0; ww < 8; ww++) rt += ms->wcnt[ww];
            total += rt;
            __syncthreads();
        }
        n_act = total;
    }

    // ---- load U^T e-half as bf16 hi/lo into smem ----
    for (int idx = tid; idx < 128 * DD; idx += 256) {
        const int d = idx >> 7, el = idx & 127;
        const float f = U[(size_t)d * DD + rank * 128 + el];
        const __nv_bfloat16 hi = __float2bfloat16(f);
        const __nv_bfloat16 lo = __float2bfloat16(f - __bfloat162float(hi));
        *(unsigned short*)(smraw + OFF_UTHI + el * PITCHB + d * 2) = __bfloat16_as_ushort(hi);
        *(unsigned short*)(smraw + OFF_UTLO + el * PITCHB + d * 2) = __bfloat16_as_ushort(lo);
    }

    // ---- zero h A-tiles (h0 = 0; rows 20..31 stay zero forever) ----
    {
        const uint4 z = make_uint4(0, 0, 0, 0);
        uint4* p = (uint4*)(smraw + OFF_HAHI);
        for (int i = tid; i < (2 * 32 * PITCHB) / 16; i += 256) p[i] = z;
    }

    // ---- kV[k][eg] for this thread's 10 k ----
    float kv[10];
#pragma unroll
    for (int j = 0; j < 10; j++) kv[j] = 0.f;
    {
        const float* kr = keys + (size_t)b * KK * DD + (size_t)kh * 10 * DD;
#pragma unroll 4
        for (int d = 0; d < DD; d++) {
            const float vv = V[(size_t)d * DD + eg];
#pragma unroll
            for (int j = 0; j < 10; j++) kv[j] = fmaf(kr[j * DD + d], vv, kv[j]);
        }
    }

    // first gate: h0 = 0 -> g = sigmoid(xk[s0])
    if (tid < KK && n_act > 0)
        ms->gbuf[tid] = 1.f / (1.f + __expf(-g_xk[((size_t)b * SS + ms->slist[0]) * KK + tid]));
    __syncthreads();
    CLUSTER_SYNC();

    // peer smem base (DSMEM)
    uint32_t peer_base;
    asm("mapa.shared::cluster.u32 %0, %1, %2;" : "=r"(peer_base) : "r"(smbase), "r"(rank ^ 1u));
    const uint32_t peer_rpart = peer_base + OFF_MISC + (uint32_t)offsetof(MiscS, rpart);

    // ldmatrix lane-constant offsets
    const int aoff = ((lane & 7) + ((lane >> 3) & 1) * 8) * PITCHB + ((lane >> 4) & 1) * 16;
    const int e0 = w * 16;
    const int boffl = (e0 + (lane & 7) + ((lane >> 4) & 1) * 8) * PITCHB + ((lane >> 3) & 1) * 16;
    const uint32_t aHI0 = smbase + OFF_HAHI + aoff;
    const uint32_t aHI1 = aHI0 + 16 * PITCHB;
    const uint32_t aLO0 = smbase + OFF_HALO + aoff;
    const uint32_t aLO1 = aLO0 + 16 * PITCHB;
    const uint32_t bHI = smbase + OFF_UTHI + boffl;
    const uint32_t bLO = smbase + OFF_UTLO + boffl;

    const int gr = lane >> 2, gc = (lane & 3) * 2;

    float h[10];
#pragma unroll
    for (int j = 0; j < 10; j++) h[j] = 0.f;

    for (int i = 0; i < n_act; i++) {
        const int s = ms->slist[i];
        const bool hasn = (i + 1 < n_act);
        const int sn = hasn ? (int)ms->slist[i + 1] : 0;
        const float xw = g_xw[((size_t)b * SS + s) * DD + eg];
        const float xn = hasn ? X[((size_t)b * SS + sn) * DD + eg] : 0.f;

        // ---- MMA phase: C[2 mtiles][2 ntiles] ----
        float c[2][2][4];
#pragma unroll
        for (int m = 0; m < 2; m++)
#pragma unroll
            for (int n = 0; n < 2; n++)
#pragma unroll
                for (int q = 0; q < 4; q++) c[m][n][q] = 0.f;

#pragma unroll 4
        for (int kc = 0; kc < 16; kc++) {
            const uint32_t dofs = (uint32_t)kc * 32;
            uint32_t ah[2][4], al[2][4], bh[4], bl[4];
            LDSM4(ah[0], aHI0 + dofs);
            LDSM4(ah[1], aHI1 + dofs);
            LDSM4(al[0], aLO0 + dofs);
            LDSM4(al[1], aLO1 + dofs);
            LDSM4(bh, bHI + dofs);
            LDSM4(bl, bLO + dofs);
#pragma unroll
            for (int m = 0; m < 2; m++) {
#pragma unroll
                for (int n = 0; n < 2; n++) {
                    MMA16816(c[m][n], ah[m], bh[2 * n], bh[2 * n + 1]);
                    MMA16816(c[m][n], ah[m], bl[2 * n], bl[2 * n + 1]);
                    MMA16816(c[m][n], al[m], bh[2 * n], bh[2 * n + 1]);
                }
            }
        }

        // ---- scatter C to accT[k][eloc] ----
#pragma unroll
        for (int n = 0; n < 2; n++) {
            const int ec = e0 + 8 * n + gc;
            *(float2*)&accT[gr * PITCHA + ec] = make_float2(c[0][n][0], c[0][n][1]);
            *(float2*)&accT[(gr + 8) * PITCHA + ec] = make_float2(c[0][n][2], c[0][n][3]);
            if (gr < 4)
                *(float2*)&accT[(16 + gr) * PITCHA + ec] = make_float2(c[1][n][0], c[1][n][1]);
        }
        __syncthreads();

        // ---- update + merged partials ----
        float upd[10], vsq[10], vdu[10];
#pragma unroll
        for (int j = 0; j < 10; j++) {
            const int k = kh * 10 + j;
            const float a = accT[k * PITCHA + eloc];
            const float t = fmaxf(a + kv[j] + xw, 0.f);
            const float u = h[j] + ms->gbuf[k] * t;
            upd[j] = u;
            vsq[j] = u * u;
            vdu[j] = xn * u;
        }
#pragma unroll
        for (int o = 16; o; o >>= 1)
#pragma unroll
            for (int j = 0; j < 10; j++) {
                vsq[j] += __shfl_xor_sync(0xffffffffu, vsq[j], o);
                vdu[j] += __shfl_xor_sync(0xffffffffu, vdu[j], o);
            }
        if (lane == 0) {
#pragma unroll
            for (int j = 0; j < 10; j++) {
                ms->red[w][j] = vsq[j];
                ms->red[w][10 + j] = vdu[j];
            }
        }
        __syncthreads();
        if (tid < KK) {
            const int kh2 = tid / 10, j2 = tid % 10;
            float sq = 0.f, du = 0.f;
#pragma unroll
            for (int ww = 0; ww < 4; ww++) {
                sq += ms->red[4 * kh2 + ww][j2];
                du += ms->red[4 * kh2 + ww][10 + j2];
            }
            ms->tot[tid] = sq;
            ms->tot[KK + tid] = du;
            asm volatile("st.shared::cluster.f32 [%0], %1;" :: "r"(peer_rpart + tid * 4), "f"(sq) : "memory");
            asm volatile("st.shared::cluster.f32 [%0], %1;" :: "r"(peer_rpart + (KK + tid) * 4), "f"(du) : "memory");
        }
        CLUSTER_SYNC();   // partials exchanged
        if (tid < KK) {
            const float sq = ms->tot[tid] + ms->rpart[tid];
            const float du = ms->tot[KK + tid] + ms->rpart[KK + tid];
            const float rinv = rsqrtf(fmaxf(sq, 1e-12f));
            ms->rbuf[tid] = rinv;
            if (hasn)
                ms->gbuf[tid] = 1.f / (1.f + __expf(-(rinv * du + g_xk[((size_t)b * SS + sn) * KK + tid])));
        }
        __syncthreads();

        // ---- normalize, write bf16 hi/lo h to local + peer A tiles ----
#pragma unroll
        for (int j = 0; j < 10; j++) {
            const int k = kh * 10 + j;
            const float hn = upd[j] * ms->rbuf[k];
            h[j] = hn;
            const __nv_bfloat16 hh = __float2bfloat16(hn);
            const __nv_bfloat16 hl = __float2bfloat16(hn - __bfloat162float(hh));
            const unsigned short hb = __bfloat16_as_ushort(hh);
            const unsigned short lb = __bfloat16_as_ushort(hl);
            const uint32_t off = (uint32_t)k * PITCHB + (uint32_t)eg * 2;
            asm volatile("st.shared.u16 [%0], %1;" :: "r"(smbase + OFF_HAHI + off), "h"(hb) : "memory");
            asm volatile("st.shared.u16 [%0], %1;" :: "r"(smbase + OFF_HALO + off), "h"(lb) : "memory");
            asm volatile("st.shared::cluster.u16 [%0], %1;" :: "r"(peer_base + OFF_HAHI + off), "h"(hb) : "memory");
            asm volatile("st.shared::cluster.u16 [%0], %1;" :: "r"(peer_base + OFF_HALO + off), "h"(lb) : "memory");
        }
        CLUSTER_SYNC();   // h tiles complete in both CTAs
    }

    // ---- emit ----
#pragma unroll
    for (int j = 0; j < 10; j++)
        out[((size_t)b * KK + kh * 10 + j) * DD + eg] = h[j];

    CLUSTER_SYNC();   // no CTA exits while its peer may still read/write DSMEM
}

extern "C" void kernel_launch(void* const* d_in, const int* in_sizes, int n_in,
                              void* d_out, int out_size) {
    const float* X = (const float*)d_in[0];                    // [B,S,D] f32
    const int* mask = (const int*)d_in[1];                     // [B,S] bool as int32
    const float* keys = (const float*)d_in[2];                 // [B,K,D] f32
    const float* U = (const float*)d_in[3];                    // [D,D] f32
    const float* V = (const float*)d_in[4];                    // [D,D] f32
    const float* W = (const float*)d_in[5];                    // [D,D] f32
    float* out = (float*)d_out;                                // [B,K,D] f32

    cudaFuncSetAttribute(rnn_mma_kernel, cudaFuncAttributeMaxDynamicSharedMemorySize, SMEM_TOT);

    xw_kernel<<<BB * (SS / 32), 256>>>(X, W);
    xk_kernel<<<BB * (SS / 8), 256>>>(X, keys);
    rnn_mma_kernel<<<2 * BB, 256, SMEM_TOT>>>(X, mask, keys, U, V, out);
}

// round 8
// speedup vs baseline: 1.8709x; 1.6338x over previous
#include <cuda_runtime.h>
#include <cuda_bf16.h>
#include <math.h>
#include <stdint.h>

// Problem constants
#define BB 256
#define SS 512
#define KK 20
#define DD 256
#define PITCHB 528   // bytes per bf16 row (264 elems): odd 16B count -> ldmatrix conflict-free
#define KVP 132      // kV table pitch (f32) -> bank-staggered per k

// Precomputed scratch (static device globals: allocation-free)
__device__ float g_xw[(size_t)BB * SS * DD];   // xW[b][s][e]
__device__ float g_xk[(size_t)BB * SS * KK];   // x.keys[b][s][k]

// ================= packed f32x2 helpers (xw kernel) =================
__device__ __forceinline__ unsigned long long f2fma(unsigned long long a,
                                                    unsigned long long b,
                                                    unsigned long long c) {
    unsigned long long d;
    asm("fma.rn.f32x2 %0, %1, %2, %3;" : "=l"(d) : "l"(a), "l"(b), "l"(c));
    return d;
}
__device__ __forceinline__ unsigned long long pk2(float a) {
    unsigned int ai = __float_as_uint(a);
    return (((unsigned long long)ai) << 32) | (unsigned long long)ai;
}
__device__ __forceinline__ void upk2(unsigned long long p, float& lo, float& hi) {
    lo = __uint_as_float((unsigned int)(p & 0xffffffffull));
    hi = __uint_as_float((unsigned int)(p >> 32));
}

// ================= PTX helpers =================
__device__ __forceinline__ uint32_t smem_u32(const void* p) {
    uint32_t a;
    asm("{ .reg .u64 t; cvta.to.shared.u64 t, %1; cvt.u32.u64 %0, t; }" : "=r"(a) : "l"(p));
    return a;
}
__device__ __forceinline__ uint32_t cluster_rank() {
    uint32_t r;
    asm("mov.u32 %0, %%cluster_ctarank;" : "=r"(r));
    return r;
}
#define CLUSTER_SYNC() do { \
    asm volatile("barrier.cluster.arrive.aligned;" ::: "memory"); \
    asm volatile("barrier.cluster.wait.aligned;" ::: "memory"); \
} while (0)

#define LDSM4(r, addr) \
    asm volatile("ldmatrix.sync.aligned.m8n8.x4.shared.b16 {%0,%1,%2,%3}, [%4];" \
        : "=r"((r)[0]), "=r"((r)[1]), "=r"((r)[2]), "=r"((r)[3]) : "r"(addr))
#define LDSM2(r, addr) \
    asm volatile("ldmatrix.sync.aligned.m8n8.x2.shared.b16 {%0,%1}, [%2];" \
        : "=r"((r)[0]), "=r"((r)[1]) : "r"(addr))

#define MMA16816(c, a, b0, b1) \
    asm volatile("mma.sync.aligned.m16n8k16.row.col.f32.bf16.bf16.f32 " \
        "{%0,%1,%2,%3}, {%4,%5,%6,%7}, {%8,%9}, {%0,%1,%2,%3};" \
        : "+f"((c)[0]), "+f"((c)[1]), "+f"((c)[2]), "+f"((c)[3]) \
        : "r"((a)[0]), "r"((a)[1]), "r"((a)[2]), "r"((a)[3]), "r"(b0), "r"(b1))

// ================= shared memory layout (dynamic) =================
struct MiscS {
    float red[8][2 * KK];      // per-warp partials (sq | du)
    float tot[2 * KK];
    float rpart[2 * KK];       // peer partials via DSMEM
    float gbuf[KK];
    float rbuf[KK];
    unsigned short slist[SS];
    int wcnt[8];
};
#define OFF_ULO 0                                 // U^T lo [128 e][256 d] bf16 (staged hi first)
#define OFF_HHI (128 * PITCHB)                    // h hi tile [24 k][256 d] bf16
#define OFF_HLO (OFF_HHI + 24 * PITCHB)           // h lo tile
#define OFF_KV  (OFF_HLO + 24 * PITCHB)           // kV [20][KVP] f32 (local e-half)
#define OFF_MISC (OFF_KV + KK * KVP * 4)
#define SMEM_TOT ((int)(OFF_MISC + sizeof(MiscS)))

// ================= kernel 1: xW[b][s][:] = x @ W =================
__global__ void __launch_bounds__(256) xw_kernel(const float* __restrict__ X,
                                                 const float* __restrict__ W) {
    __shared__ float xt[DD][34];
    const int cta = blockIdx.x;
    const int b = cta >> 4;
    const int s0 = (cta & 15) * 32;
    const int tid = threadIdx.x;

    for (int idx = tid; idx < 32 * DD; idx += 256) {
        const int ss = idx >> 8, d = idx & 255;
        xt[d][ss] = X[((size_t)(b * SS + s0 + ss)) * DD + d];
    }
    __syncthreads();

    unsigned long long acc[16];
#pragma unroll
    for (int i = 0; i < 16; i++) acc[i] = 0ull;

    float ua[4], ub[4], un[4];
#pragma unroll
    for (int j = 0; j < 4; j++) ua[j] = W[j * DD + tid];
#pragma unroll
    for (int j = 0; j < 4; j++) ub[j] = W[(4 + j) * DD + tid];
    for (int db = 0; db < 64; db++) {
        const int dn = db * 4 + 8;
        if (dn < DD) {
#pragma unroll
            for (int j = 0; j < 4; j++) un[j] = W[(dn + j) * DD + tid];
        } else {
#pragma unroll
            for (int j = 0; j < 4; j++) un[j] = 0.f;
        }
#pragma unroll
        for (int dd = 0; dd < 4; dd++) {
            const int d = db * 4 + dd;
            const unsigned long long* xr = (const unsigned long long*)xt[d];
            unsigned long long ww = pk2(ua[dd]);
#pragma unroll
            for (int j = 0; j < 16; j++) acc[j] = f2fma(xr[j], ww, acc[j]);
        }
#pragma unroll
        for (int j = 0; j < 4; j++) { ua[j] = ub[j]; ub[j] = un[j]; }
    }
#pragma unroll
    for (int j = 0; j < 16; j++) {
        float lo, hi;
        upk2(acc[j], lo, hi);
        g_xw[((size_t)b * SS + s0 + 2 * j) * DD + tid] = lo;
        g_xw[((size_t)b * SS + s0 + 2 * j + 1) * DD + tid] = hi;
    }
}

// ================= kernel 1b: xk[b][s][k] = x . keys[b][k] =================
__global__ void __launch_bounds__(256) xk_kernel(const float* __restrict__ X,
                                                 const float* __restrict__ keys) {
    const int b = blockIdx.x >> 6;
    const int s = ((blockIdx.x & 63) << 3) + (threadIdx.x >> 5);
    const int lane = threadIdx.x & 31;
    const float* x = X + ((size_t)b * SS + s) * DD;
    const float* kb = keys + (size_t)b * KK * DD;

    float xr[8];
#pragma unroll
    for (int c = 0; c < 8; c++) xr[c] = x[lane + 32 * c];

    float pk[KK];
#pragma unroll
    for (int k = 0; k < KK; k++) {
        float p = 0.f;
#pragma unroll
        for (int c = 0; c < 8; c++) p = fmaf(xr[c], kb[k * DD + lane + 32 * c], p);
        pk[k] = p;
    }
#pragma unroll
    for (int o = 16; o; o >>= 1)
#pragma unroll
        for (int k = 0; k < KK; k++) pk[k] += __shfl_xor_sync(0xffffffffu, pk[k], o);

    if (lane < KK)
        g_xk[((size_t)b * SS + s) * KK + lane] = pk[lane];
}

// ================= kernel 2: HMMA recurrent kernel, C[e][k], 2 CTAs/SM =================
__global__ void __launch_bounds__(256, 2) __cluster_dims__(2, 1, 1)
rnn_mma_kernel(const float* __restrict__ X, const int* __restrict__ mask,
               const float* __restrict__ keys, const float* __restrict__ U,
               const float* __restrict__ V, float* __restrict__ out) {
    extern __shared__ __align__(16) unsigned char smraw[];
    MiscS* ms = (MiscS*)(smraw + OFF_MISC);
    float* kVs = (float*)(smraw + OFF_KV);

    const int tid = threadIdx.x;
    const int lane = tid & 31, w = tid >> 5;
    const int b = blockIdx.x >> 1;
    const uint32_t rank = cluster_rank();
    const uint32_t smbase = smem_u32(smraw);

    const int e0 = w * 16;
    const int gr = lane >> 2;
    const int gc = (lane & 3) * 2;
    const int el0 = e0 + gr;        // local e, rr=0
    const int el1 = e0 + 8 + gr;    // local e, rr=1
    const int eg0 = (int)rank * 128 + el0;
    const int eg1 = (int)rank * 128 + el1;

    // ---- mask compaction ----
    int n_act = 0;
    {
        int total = 0;
        for (int r = 0; r < 2; r++) {
            const int idx = r * 256 + tid;
            const int m = (mask[b * SS + idx] != 0);
            const unsigned bal = __ballot_sync(0xffffffffu, m);
            const int pre = __popc(bal & ((1u << lane) - 1));
            if (lane == 0) ms->wcnt[w] = __popc(bal);
            __syncthreads();
            int woff = 0;
            for (int ww = 0; ww < w; ww++) woff += ms->wcnt[ww];
            if (m) ms->slist[total + woff + pre] = (unsigned short)idx;
            int rt = 0;
#pragma unroll
            for (int ww = 0; ww < 8; ww++) rt += ms->wcnt[ww];
            total += rt;
            __syncthreads();
        }
        n_act = total;
    }

    // ---- stage U^T HI into ULO region, preload A frags, then overwrite with LO ----
    for (int idx = tid; idx < 128 * DD; idx += 256) {
        const int el = idx & 127, d = idx >> 7;
        const float f = U[(size_t)d * DD + rank * 128 + el];
        *(unsigned short*)(smraw + OFF_ULO + el * PITCHB + d * 2) =
            __bfloat16_as_ushort(__float2bfloat16(f));
    }
    __syncthreads();

    // A-fragment ldmatrix offset (rows = e within warp)
    const uint32_t aoff = (uint32_t)(e0 + (lane & 7) + ((lane >> 3) & 1) * 8) * PITCHB
                        + (uint32_t)((lane >> 4) & 1) * 16;
    uint32_t uh[16][4];
#pragma unroll
    for (int kc = 0; kc < 16; kc++)
        LDSM4(uh[kc], smbase + OFF_ULO + aoff + (uint32_t)kc * 32);
    __syncthreads();

    for (int idx = tid; idx < 128 * DD; idx += 256) {
        const int el = idx & 127, d = idx >> 7;
        const float f = U[(size_t)d * DD + rank * 128 + el];
        const __nv_bfloat16 hi = __float2bfloat16(f);
        *(unsigned short*)(smraw + OFF_ULO + el * PITCHB + d * 2) =
            __bfloat16_as_ushort(__float2bfloat16(f - __bfloat162float(hi)));
    }

    // zero h tiles (rows 20..23 stay zero forever)
    {
        const uint4 z = make_uint4(0, 0, 0, 0);
        uint4* p = (uint4*)(smraw + OFF_HHI);
        for (int i = tid; i < (2 * 24 * PITCHB) / 16; i += 256) p[i] = z;
    }

    // kV table [20][KVP] for local e-half
    {
        const int kh = tid >> 7, el = tid & 127;
        float kvv[10];
#pragma unroll
        for (int j = 0; j < 10; j++) kvv[j] = 0.f;
        const float* kr = keys + (size_t)b * KK * DD + (size_t)kh * 10 * DD;
#pragma unroll 4
        for (int d = 0; d < DD; d++) {
            const float vv = V[(size_t)d * DD + rank * 128 + el];
#pragma unroll
            for (int j = 0; j < 10; j++) kvv[j] = fmaf(kr[j * DD + d], vv, kvv[j]);
        }
#pragma unroll
        for (int j = 0; j < 10; j++) kVs[(kh * 10 + j) * KVP + el] = kvv[j];
    }

    if (tid < KK && n_act > 0)
        ms->gbuf[tid] = 1.f / (1.f + __expf(-g_xk[((size_t)b * SS + ms->slist[0]) * KK + tid]));
    __syncthreads();
    CLUSTER_SYNC();

    uint32_t peer_base;
    asm("mapa.shared::cluster.u32 %0, %1, %2;" : "=r"(peer_base) : "r"(smbase), "r"(rank ^ 1u));
    const uint32_t peer_rpart = peer_base + OFF_MISC + (uint32_t)offsetof(MiscS, rpart);

    // B-fragment offsets (rows = k of h tile)
    const uint32_t bOff4 = (uint32_t)(8 * ((lane >> 4) & 1) + (lane & 7)) * PITCHB
                         + (uint32_t)((lane >> 3) & 1) * 16;
    const uint32_t bOff2 = (uint32_t)(16 + (lane & 7)) * PITCHB
                         + (uint32_t)((lane >> 3) & 1) * 16;
    const uint32_t hhi = smbase + OFF_HHI, hlo = smbase + OFF_HLO;
    const uint32_t ulo = smbase + OFF_ULO;

    for (int i = 0; i < n_act; i++) {
        const int s = ms->slist[i];
        const bool hasn = (i + 1 < n_act);
        const int sn = hasn ? (int)ms->slist[i + 1] : 0;
        const float xw0 = g_xw[((size_t)b * SS + s) * DD + eg0];
        const float xw1 = g_xw[((size_t)b * SS + s) * DD + eg1];
        float xn0 = 0.f, xn1 = 0.f;
        if (hasn) {
            xn0 = X[((size_t)b * SS + sn) * DD + eg0];
            xn1 = X[((size_t)b * SS + sn) * DD + eg1];
        }

        // ---- MMA: c[nt] = sum_d U^T[e][d]*h[k][d] over 3 hi/lo passes ----
        float c[3][4];
#pragma unroll
        for (int nt = 0; nt < 3; nt++)
#pragma unroll
            for (int q = 0; q < 4; q++) c[nt][q] = 0.f;

#pragma unroll
        for (int kc = 0; kc < 16; kc++) {
            const uint32_t dofs = (uint32_t)kc * 32;
            uint32_t bh[4], b2[2], al[4], bl[4], bl2[2];
            LDSM4(bh, hhi + bOff4 + dofs);
            LDSM2(b2, hhi + bOff2 + dofs);
            LDSM4(al, ulo + aoff + dofs);
            MMA16816(c[0], uh[kc], bh[0], bh[1]);
            MMA16816(c[1], uh[kc], bh[2], bh[3]);
            MMA16816(c[2], uh[kc], b2[0], b2[1]);
            MMA16816(c[0], al, bh[0], bh[1]);
            MMA16816(c[1], al, bh[2], bh[3]);
            MMA16816(c[2], al, b2[0], b2[1]);
            LDSM4(bl, hlo + bOff4 + dofs);
            LDSM2(bl2, hlo + bOff2 + dofs);
            MMA16816(c[0], uh[kc], bl[0], bl[1]);
            MMA16816(c[1], uh[kc], bl[2], bl[3]);
            MMA16816(c[2], uh[kc], bl2[0], bl2[1]);
        }

        // ---- in-register update + partials ----
        float sq6[6], du6[6];
#pragma unroll
        for (int nt = 0; nt < 3; nt++) {
#pragma unroll
            for (int j = 0; j < 2; j++) {
                const int k = 8 * nt + gc + j;
                const bool val = (k < KK);
                const int kk = val ? k : 0;
                const float gv = val ? ms->gbuf[kk] : 0.f;
                const float kv0 = kVs[kk * KVP + el0];
                const float kv1 = kVs[kk * KVP + el1];
                float u0 = 0.f, u1 = 0.f;
                if (val) {
                    const unsigned short h0h = *(unsigned short*)(smraw + OFF_HHI + kk * PITCHB + eg0 * 2);
                    const unsigned short h0l = *(unsigned short*)(smraw + OFF_HLO + kk * PITCHB + eg0 * 2);
                    const unsigned short h1h = *(unsigned short*)(smraw + OFF_HHI + kk * PITCHB + eg1 * 2);
                    const unsigned short h1l = *(unsigned short*)(smraw + OFF_HLO + kk * PITCHB + eg1 * 2);
                    const float ho0 = __bfloat162float(__ushort_as_bfloat16(h0h)) +
                                      __bfloat162float(__ushort_as_bfloat16(h0l));
                    const float ho1 = __bfloat162float(__ushort_as_bfloat16(h1h)) +
                                      __bfloat162float(__ushort_as_bfloat16(h1l));
                    u0 = ho0 + gv * fmaxf(c[nt][j] + kv0 + xw0, 0.f);
                    u1 = ho1 + gv * fmaxf(c[nt][2 + j] + kv1 + xw1, 0.f);
                }
                c[nt][j] = u0;
                c[nt][2 + j] = u1;
                sq6[2 * nt + j] = u0 * u0 + u1 * u1;
                du6[2 * nt + j] = xn0 * u0 + xn1 * u1;
            }
        }
#pragma unroll
        for (int o = 4; o <= 16; o <<= 1)
#pragma unroll
            for (int q = 0; q < 6; q++) {
                sq6[q] += __shfl_xor_sync(0xffffffffu, sq6[q], o);
                du6[q] += __shfl_xor_sync(0xffffffffu, du6[q], o);
            }
        if (lane < 4) {
#pragma unroll
            for (int q = 0; q < 6; q++) {
                const int k = 8 * (q >> 1) + gc + (q & 1);
                if (k < KK) {
                    ms->red[w][k] = sq6[q];
                    ms->red[w][KK + k] = du6[q];
                }
            }
        }
        __syncthreads();
        if (tid < KK) {
            float sq = 0.f, du = 0.f;
#pragma unroll
            for (int ww = 0; ww < 8; ww++) {
                sq += ms->red[ww][tid];
                du += ms->red[ww][KK + tid];
            }
            ms->tot[tid] = sq;
            ms->tot[KK + tid] = du;
            asm volatile("st.shared::cluster.f32 [%0], %1;" :: "r"(peer_rpart + tid * 4), "f"(sq) : "memory");
            asm volatile("st.shared::cluster.f32 [%0], %1;" :: "r"(peer_rpart + (KK + tid) * 4), "f"(du) : "memory");
        }
        CLUSTER_SYNC();
        if (tid < KK) {
            const float sq = ms->tot[tid] + ms->rpart[tid];
            const float du = ms->tot[KK + tid] + ms->rpart[KK + tid];
            const float rinv = rsqrtf(fmaxf(sq, 1e-12f));
            ms->rbuf[tid] = rinv;
            if (hasn)
                ms->gbuf[tid] = 1.f / (1.f + __expf(-(rinv * du + g_xk[((size_t)b * SS + sn) * KK + tid])));
        }
        __syncthreads();

        // ---- normalize + write h bf16 hi/lo to local + peer tiles ----
#pragma unroll
        for (int nt = 0; nt < 3; nt++) {
#pragma unroll
            for (int j = 0; j < 2; j++) {
                const int k = 8 * nt + gc + j;
                if (k < KK) {
                    const float rv = ms->rbuf[k];
                    const uint32_t roff = (uint32_t)k * PITCHB;
#pragma unroll
                    for (int rr = 0; rr < 2; rr++) {
                        const float hn = c[nt][2 * rr + j] * rv;
                        const __nv_bfloat16 hh = __float2bfloat16(hn);
                        const __nv_bfloat16 hl = __float2bfloat16(hn - __bfloat162float(hh));
                        const unsigned short hb = __bfloat16_as_ushort(hh);
                        const unsigned short lb = __bfloat16_as_ushort(hl);
                        const uint32_t off = roff + (uint32_t)(rr ? eg1 : eg0) * 2;
                        asm volatile("st.shared.u16 [%0], %1;" :: "r"(smbase + OFF_HHI + off), "h"(hb) : "memory");
                        asm volatile("st.shared.u16 [%0], %1;" :: "r"(smbase + OFF_HLO + off), "h"(lb) : "memory");
                        asm volatile("st.shared::cluster.u16 [%0], %1;" :: "r"(peer_base + OFF_HHI + off), "h"(hb) : "memory");
                        asm volatile("st.shared::cluster.u16 [%0], %1;" :: "r"(peer_base + OFF_HLO + off), "h"(lb) : "memory");
                    }
                }
            }
        }
        CLUSTER_SYNC();
    }

    // ---- emit: h = hi + lo from tiles ----
    {
        const int kh = tid >> 7, el = tid & 127;
        const int eg = (int)rank * 128 + el;
#pragma unroll
        for (int j = 0; j < 10; j++) {
            const int k = kh * 10 + j;
            const unsigned short hb = *(unsigned short*)(smraw + OFF_HHI + k * PITCHB + eg * 2);
            const unsigned short lb = *(unsigned short*)(smraw + OFF_HLO + k * PITCHB + eg * 2);
            out[((size_t)b * KK + k) * DD + eg] =
                __bfloat162float(__ushort_as_bfloat16(hb)) + __bfloat162float(__ushort_as_bfloat16(lb));
        }
    }
    CLUSTER_SYNC();   // no CTA exits while peer DSMEM traffic may be in flight
}

extern "C" void kernel_launch(void* const* d_in, const int* in_sizes, int n_in,
                              void* d_out, int out_size) {
    const float* X = (const float*)d_in[0];                    // [B,S,D] f32
    const int* mask = (const int*)d_in[1];                     // [B,S] bool as int32
    const float* keys = (const float*)d_in[2];                 // [B,K,D] f32
    const float* U = (const float*)d_in[3];                    // [D,D] f32
    const float* V = (const float*)d_in[4];                    // [D,D] f32
    const float* W = (const float*)d_in[5];                    // [D,D] f32
    float* out = (float*)d_out;                                // [B,K,D] f32

    cudaFuncSetAttribute(rnn_mma_kernel, cudaFuncAttributeMaxDynamicSharedMemorySize, SMEM_TOT);

    xw_kernel<<<BB * (SS / 32), 256>>>(X, W);
    xk_kernel<<<BB * (SS / 8), 256>>>(X, keys);
    rnn_mma_kernel<<<2 * BB, 256, SMEM_TOT>>>(X, mask, keys, U, V, out);
}